// round 14
// baseline (speedup 1.0000x reference)
#include <cuda_runtime.h>
#include <cuda_fp16.h>
#include <stdint.h>
#include <math.h>

#define NN 30000
#define NE 480000
#define NG 300
#define NDIM 64
#define EDIM 41
#define NCONV 6
#define EPSV 1e-5f
#define KPAD 48
#define KP2 72
#define SLEN 64   // sorted edges per warp in k_applyS

// ---- scratch (static device globals; no runtime allocation) ----
__device__ float g_nf[NN * NDIM];
__device__ __half g_P[NN * 256];             // fp16 (15.4 MB, L2-resident)
__device__ __half g_z[(size_t)NE * 128];     // per-layer pre-BN z, SORTED row order (123 MB)
__device__ __half g_w3[NCONV * 128 * KPAD];
__device__ __half g_ea16[(size_t)NE * KPAD];
__device__ float g_agg[NN * NDIM];
__device__ float g_stats[256];
__device__ float g_sb[256];
__device__ float g_gsum[NG * NDIM];
__device__ float g_gcnt[NG];
__device__ int g_hist[NN];                   // dst histogram
__device__ int g_cur[NN];                    // working offsets for scatter
__device__ int g_ipos[NE];                   // original edge -> sorted position
__device__ int g_dstS[NE];                   // dst by sorted position

__device__ __forceinline__ float sp_f(float x) {
    return x > 20.f ? x : log1pf(__expf(x));
}
__device__ __forceinline__ float sig_f(float x) {
    return 1.f / (1.f + __expf(-x));
}

#define MMA_F16(c0,c1,c2,c3,a0,a1,a2,a3,b0,b1) \
  asm volatile("mma.sync.aligned.m16n8k16.row.col.f32.f16.f16.f32 " \
      "{%0,%1,%2,%3}, {%4,%5,%6,%7}, {%8,%9}, {%0,%1,%2,%3};" \
      : "+f"(c0),"+f"(c1),"+f"(c2),"+f"(c3) \
      : "r"(a0),"r"(a1),"r"(a2),"r"(a3),"r"(b0),"r"(b1))

// ---------------- embed ----------------
__global__ void k_embed(const float* __restrict__ x,
                        const float* __restrict__ embW,
                        const float* __restrict__ embB) {
    int c = threadIdx.x;
    float w[92];
#pragma unroll
    for (int k = 0; k < 92; k++) w[k] = embW[k * 64 + c];
    float b = embB[c];
    __shared__ float xs[8][92];
    int v0 = blockIdx.x * 8;
    for (int i = threadIdx.x; i < 8 * 92; i += 64) {
        int n = i / 92, k = i % 92;
        int v = v0 + n;
        xs[n][k] = (v < NN) ? x[v * 92 + k] : 0.f;
    }
    __syncthreads();
#pragma unroll 2
    for (int n = 0; n < 8; n++) {
        int v = v0 + n;
        if (v >= NN) break;
        float acc = b;
#pragma unroll
        for (int k = 0; k < 92; k++) acc += xs[n][k] * w[k];
        g_nf[v * 64 + c] = acc;
    }
}

// ---------------- prep: weights + edge_attr to fp16 ----------------
__global__ void k_prepw(const float* __restrict__ convW) {
    int i = blockIdx.x * 256 + threadIdx.x;
    if (i >= NCONV * 128 * KPAD) return;
    int n = i / KPAD, k = i - n * KPAD;
    int l = n >> 7, c = n & 127;
    float v = (k < EDIM) ? convW[(l * 169 + 128 + k) * 128 + c] : 0.f;
    g_w3[i] = __float2half(v);
}

__global__ void k_prepea(const float* __restrict__ ea) {
    size_t i = (size_t)blockIdx.x * 256 + threadIdx.x;
    if (i >= (size_t)NE * KPAD) return;
    size_t e = i / KPAD;
    int k = (int)(i - e * KPAD);
    g_ea16[i] = __float2half((k < EDIM) ? ea[e * EDIM + k] : 0.f);
}

// ---------------- launch-level zero (incl. dst histogram) ----------------
__global__ void k_zero0() {
    int i = blockIdx.x * blockDim.x + threadIdx.x;
    if (i < NN * NDIM) g_agg[i] = 0.f;
    if (i < 256) g_stats[i] = 0.f;
    if (i < NG * NDIM) g_gsum[i] = 0.f;
    if (i < NG) g_gcnt[i] = 0.f;
    if (i < NN) g_hist[i] = 0;
}

// ---------------- counting sort of edges by dst (per launch; eidx constant) ----------------
__global__ void k_hist(const int* __restrict__ eidx) {
    int i = blockIdx.x * 256 + threadIdx.x;
    if (i < NE) atomicAdd(&g_hist[eidx[NE + i]], 1);
}

__global__ void k_scan() {
    // 1 block, 1024 threads; each scans a 30-bin chunk (1000*30 = 30000)
    __shared__ int part[1024];
    int t = threadIdx.x;
    int base = t * 30;
    int s = 0;
    if (base < NN)
#pragma unroll
        for (int i = 0; i < 30; i++) s += g_hist[base + i];
    part[t] = s;
    __syncthreads();
    for (int off = 1; off < 1024; off <<= 1) {
        int v = (t >= off) ? part[t - off] : 0;
        __syncthreads();
        part[t] += v;
        __syncthreads();
    }
    if (base < NN) {
        int run = (t == 0) ? 0 : part[t - 1];
#pragma unroll
        for (int i = 0; i < 30; i++) {
            g_cur[base + i] = run;
            run += g_hist[base + i];
        }
    }
}

__global__ void k_scatter(const int* __restrict__ eidx) {
    int e = blockIdx.x * 256 + threadIdx.x;
    if (e >= NE) return;
    int d = eidx[NE + e];
    int pos = atomicAdd(&g_cur[d], 1);
    g_ipos[e] = pos;
    g_dstS[pos] = d;
}

// ---------------- P = nf @ [W_dst | W_src] via fp16 mma ----------------
__global__ void k_pgemm16(const float* __restrict__ convW, int l) {
    __shared__ __half Ah[64 * KP2];
    __shared__ __half Bh[128 * KP2];
    int tid = threadIdx.x;
    int m0 = blockIdx.x * 64;
    int half_id = blockIdx.y;

    for (int idx = tid; idx < 64 * 64; idx += 256) {
        int r = idx >> 6, k = idx & 63;
        int v = m0 + r;
        Ah[r * KP2 + k] = __float2half((v < NN) ? g_nf[v * 64 + k] : 0.f);
    }
    const float* W = convW + (l * 169 + half_id * 64) * 128;
    for (int idx = tid; idx < 128 * 64; idx += 256) {
        int k = idx >> 7, n = idx & 127;
        Bh[n * KP2 + k] = __float2half(W[k * 128 + n]);
    }
    __syncthreads();

    int w = tid >> 5, lane = tid & 31;
    int wm = w & 3, wn = w >> 2;
    int g = lane >> 2, tq = lane & 3;
    float acc[32];
#pragma unroll
    for (int i = 0; i < 32; i++) acc[i] = 0.f;
    int ar0 = wm * 16 + g;

#pragma unroll
    for (int ks = 0; ks < 4; ks++) {
        int kb = ks * 16 + tq * 2;
        uint32_t a0 = *(const uint32_t*)&Ah[ar0 * KP2 + kb];
        uint32_t a1 = *(const uint32_t*)&Ah[(ar0 + 8) * KP2 + kb];
        uint32_t a2 = *(const uint32_t*)&Ah[ar0 * KP2 + kb + 8];
        uint32_t a3 = *(const uint32_t*)&Ah[(ar0 + 8) * KP2 + kb + 8];
#pragma unroll
        for (int ns = 0; ns < 8; ns++) {
            int bn = wn * 64 + ns * 8 + g;
            uint32_t b0 = *(const uint32_t*)&Bh[bn * KP2 + kb];
            uint32_t b1 = *(const uint32_t*)&Bh[bn * KP2 + kb + 8];
            float* c = acc + ns * 4;
            MMA_F16(c[0], c[1], c[2], c[3], a0, a1, a2, a3, b0, b1);
        }
    }

    int row0 = m0 + wm * 16 + g;
#pragma unroll
    for (int ns = 0; ns < 8; ns++) {
        int col = half_id * 128 + wn * 64 + ns * 8 + tq * 2;
        if (row0 < NN)
            ((__half2*)g_P)[((size_t)row0 * 256 + col) >> 1] =
                __floats2half2_rn(acc[ns * 4 + 0], acc[ns * 4 + 1]);
        if (row0 + 8 < NN)
            ((__half2*)g_P)[((size_t)(row0 + 8) * 256 + col) >> 1] =
                __floats2half2_rn(acc[ns * 4 + 2], acc[ns * 4 + 3]);
    }
}

// ---------------- fused: z = ea@W3 + P1[dst] + P2[src]; z stored at SORTED pos; BN stats ----------------
__global__ void k_ewfused16(const int* __restrict__ eidx, int l) {
    __shared__ __half Ah[64 * KPAD];
    __shared__ __half Bh[128 * KPAD];
    __shared__ float sred[256];
    int tid = threadIdx.x;
    int m0 = blockIdx.x * 64;

    int w = tid >> 5, lane = tid & 31;
    int wm = w & 3, wn = w >> 2;
    int g = lane >> 2, tq = lane & 3;

    // ---- prefetch indices + sorted positions + P gathers (independent of MMA) ----
    int r0 = wm * 16 + g, r1 = r0 + 8;
    int d0 = eidx[NE + m0 + r0], s0 = eidx[m0 + r0];
    int d1 = eidx[NE + m0 + r1], s1 = eidx[m0 + r1];
    int zp0 = g_ipos[m0 + r0], zp1 = g_ipos[m0 + r1];
    __half2 pd0[8], ps0[8], pd1[8], ps1[8];
#pragma unroll
    for (int ns = 0; ns < 8; ns++) {
        int col = wn * 64 + ns * 8 + tq * 2;
        pd0[ns] = *(const __half2*)&g_P[(size_t)d0 * 256 + col];
        ps0[ns] = *(const __half2*)&g_P[(size_t)s0 * 256 + 128 + col];
        pd1[ns] = *(const __half2*)&g_P[(size_t)d1 * 256 + col];
        ps1[ns] = *(const __half2*)&g_P[(size_t)s1 * 256 + 128 + col];
    }

    sred[tid] = 0.f;
    const uint32_t* easrc = (const uint32_t*)(g_ea16 + (size_t)m0 * KPAD);
    for (int idx = tid; idx < 64 * KPAD / 2; idx += 256)
        ((uint32_t*)Ah)[idx] = easrc[idx];
    const uint32_t* w3 = (const uint32_t*)(g_w3 + l * 128 * KPAD);
    for (int idx = tid; idx < 128 * KPAD / 2; idx += 256)
        ((uint32_t*)Bh)[idx] = w3[idx];
    __syncthreads();

    float acc[32];
#pragma unroll
    for (int i = 0; i < 32; i++) acc[i] = 0.f;
    int ar0 = wm * 16 + g;

#pragma unroll
    for (int ks = 0; ks < 3; ks++) {
        int kb = ks * 16 + tq * 2;
        uint32_t a0 = *(const uint32_t*)&Ah[ar0 * KPAD + kb];
        uint32_t a1 = *(const uint32_t*)&Ah[(ar0 + 8) * KPAD + kb];
        uint32_t a2 = *(const uint32_t*)&Ah[ar0 * KPAD + kb + 8];
        uint32_t a3 = *(const uint32_t*)&Ah[(ar0 + 8) * KPAD + kb + 8];
#pragma unroll
        for (int ns = 0; ns < 8; ns++) {
            int bn = wn * 64 + ns * 8 + g;
            uint32_t b0 = *(const uint32_t*)&Bh[bn * KPAD + kb];
            uint32_t b1 = *(const uint32_t*)&Bh[bn * KPAD + kb + 8];
            float* c = acc + ns * 4;
            MMA_F16(c[0], c[1], c[2], c[3], a0, a1, a2, a3, b0, b1);
        }
    }

#pragma unroll
    for (int ns = 0; ns < 8; ns++) {
        int col = wn * 64 + ns * 8 + tq * 2;
        float2 fd0 = __half22float2(pd0[ns]);
        float2 fs0 = __half22float2(ps0[ns]);
        float2 fd1 = __half22float2(pd1[ns]);
        float2 fs1 = __half22float2(ps1[ns]);
        float z00 = acc[ns * 4 + 0] + fd0.x + fs0.x;
        float z01 = acc[ns * 4 + 1] + fd0.y + fs0.y;
        float z10 = acc[ns * 4 + 2] + fd1.x + fs1.x;
        float z11 = acc[ns * 4 + 3] + fd1.y + fs1.y;
        ((__half2*)g_z)[((size_t)zp0 * 128 + col) >> 1] = __floats2half2_rn(z00, z01);
        ((__half2*)g_z)[((size_t)zp1 * 128 + col) >> 1] = __floats2half2_rn(z10, z11);
        acc[ns * 4 + 0] = z00 + z10;
        acc[ns * 4 + 1] = z01 + z11;
        acc[ns * 4 + 2] = z00 * z00 + z10 * z10;
        acc[ns * 4 + 3] = z01 * z01 + z11 * z11;
    }
#pragma unroll
    for (int off = 4; off <= 16; off <<= 1) {
#pragma unroll
        for (int i = 0; i < 32; i++)
            acc[i] += __shfl_xor_sync(0xffffffff, acc[i], off);
    }
    if (g == 0) {
#pragma unroll
        for (int ns = 0; ns < 8; ns++) {
            int col = wn * 64 + ns * 8 + tq * 2;
            atomicAdd(&sred[col],       acc[ns * 4 + 0]);
            atomicAdd(&sred[col + 1],   acc[ns * 4 + 1]);
            atomicAdd(&sred[128 + col], acc[ns * 4 + 2]);
            atomicAdd(&sred[129 + col], acc[ns * 4 + 3]);
        }
    }
    __syncthreads();
    atomicAdd(&g_stats[tid], sred[tid]);
}

// ---------------- finalize BN stats -> scale/bias (self-zero stats) ----------------
__global__ void k_stats(const float* __restrict__ bnG,
                        const float* __restrict__ bnB, int l) {
    int c = threadIdx.x;
    float inv = 1.f / (float)NE;
    float mu = g_stats[c] * inv;
    float var = g_stats[128 + c] * inv - mu * mu;
    float sc = rsqrtf(var + EPSV) * bnG[l * 128 + c];
    g_sb[c] = sc;
    g_sb[128 + c] = bnB[l * 128 + c] - mu * sc;
    g_stats[c] = 0.f;
    g_stats[128 + c] = 0.f;
}

// ---------------- applyS: sorted z stream, register run-accumulation, few atomics ----------------
__global__ void k_applyS() {
    __shared__ float sb[256];
    int tid = threadIdx.x;
    sb[tid] = g_sb[tid];
    __syncthreads();
    int wid = tid >> 5, lane = tid & 31;
    int j = lane * 2;   // column pair 0..62
    int e0 = (blockIdx.x * 8 + wid) * SLEN;
    float sc1a = sb[j],       sc1b = sb[j + 1];
    float bi1a = sb[128 + j], bi1b = sb[129 + j];
    float sc2a = sb[64 + j],  sc2b = sb[65 + j];
    float bi2a = sb[192 + j], bi2b = sb[193 + j];
    float accA = 0.f, accB = 0.f;
    int cur = -1;
    for (int i = 0; i < SLEN; i++) {
        int e = e0 + i;
        if (e >= NE) break;
        int d = g_dstS[e];
        if (d != cur) {
            if (cur >= 0) {
                atomicAdd(&g_agg[(size_t)cur * 64 + j], accA);
                atomicAdd(&g_agg[(size_t)cur * 64 + j + 1], accB);
            }
            cur = d; accA = 0.f; accB = 0.f;
        }
        __half2 a = *((const __half2*)&g_z[(size_t)e * 128 + j]);
        __half2 b = *((const __half2*)&g_z[(size_t)e * 128 + 64 + j]);
        float z1a = __low2float(a) * sc1a + bi1a;
        float z1b = __high2float(a) * sc1b + bi1b;
        float z2a = __low2float(b) * sc2a + bi2a;
        float z2b = __high2float(b) * sc2b + bi2b;
        accA += sig_f(z1a) * sp_f(z2a);
        accB += sig_f(z1b) * sp_f(z2b);
    }
    if (cur >= 0) {
        atomicAdd(&g_agg[(size_t)cur * 64 + j], accA);
        atomicAdd(&g_agg[(size_t)cur * 64 + j + 1], accB);
    }
}

// ---------------- node update (self-zero agg) ----------------
__global__ void k_node(const float* __restrict__ lnG,
                       const float* __restrict__ lnB, int l) {
    int v = blockIdx.x * 4 + (threadIdx.x >> 5);
    int lane = threadIdx.x & 31;
    if (v >= NN) return;
    float a0 = g_agg[v * 64 + lane];
    float a1 = g_agg[v * 64 + 32 + lane];
    g_agg[v * 64 + lane] = 0.f;
    g_agg[v * 64 + 32 + lane] = 0.f;
    float s = a0 + a1;
    float sq = a0 * a0 + a1 * a1;
#pragma unroll
    for (int o = 16; o > 0; o >>= 1) {
        s  += __shfl_xor_sync(0xffffffff, s, o);
        sq += __shfl_xor_sync(0xffffffff, sq, o);
    }
    float mu = s * (1.f / 64.f);
    float var = sq * (1.f / 64.f) - mu * mu;
    float rs = rsqrtf(var + EPSV);
    float l0 = (a0 - mu) * rs * lnG[l * 64 + lane] + lnB[l * 64 + lane];
    float l1 = (a1 - mu) * rs * lnG[l * 64 + 32 + lane] + lnB[l * 64 + 32 + lane];
    g_nf[v * 64 + lane]      = sp_f(l0 + g_nf[v * 64 + lane]);
    g_nf[v * 64 + 32 + lane] = sp_f(l1 + g_nf[v * 64 + 32 + lane]);
}

// ---------------- pooling ----------------
__global__ void k_pool(const int* __restrict__ batch) {
    int tid = blockIdx.x * blockDim.x + threadIdx.x;
    int v = tid >> 6;
    int c = tid & 63;
    if (v >= NN) return;
    int g = batch[v];
    atomicAdd(&g_gsum[g * 64 + c], g_nf[v * 64 + c]);
    if (c == 0) atomicAdd(&g_gcnt[g], 1.f);
}

// ---------------- final MLP head ----------------
__global__ void k_mlp(const float* __restrict__ fc1W, const float* __restrict__ fc1B,
                      const float* __restrict__ fcsW, const float* __restrict__ fcsB,
                      const float* __restrict__ foW, const float* __restrict__ foB,
                      float* __restrict__ out) {
    int g = blockIdx.x;
    int c = threadIdx.x;
    __shared__ float s[64];
    __shared__ float h[128];
    __shared__ float red[128];

    if (c < 64) {
        float cnt = g_gcnt[g];
        s[c] = g_gsum[g * 64 + c] / fmaxf(cnt, 1.f);
    }
    __syncthreads();
    float acc = fc1B[c];
#pragma unroll 4
    for (int k = 0; k < 64; k++) acc += s[k] * fc1W[k * 128 + c];
    h[c] = sp_f(acc);
    __syncthreads();
    for (int lh = 0; lh < 3; lh++) {
        float a = fcsB[lh * 128 + c];
#pragma unroll 4
        for (int k = 0; k < 128; k++) a += h[k] * fcsW[(lh * 128 + k) * 128 + c];
        __syncthreads();
        h[c] = sp_f(a);
        __syncthreads();
    }
    red[c] = h[c] * foW[c];
    __syncthreads();
#pragma unroll
    for (int o = 64; o > 0; o >>= 1) {
        if (c < o) red[c] += red[c + o];
        __syncthreads();
    }
    if (c == 0) out[g] = red[0] + foB[0];
}

// ---------------- launch ----------------
extern "C" void kernel_launch(void* const* d_in, const int* in_sizes, int n_in,
                              void* d_out, int out_size) {
    const float* x        = (const float*)d_in[0];
    const float* edge_attr= (const float*)d_in[1];
    const float* embW     = (const float*)d_in[2];
    const float* embB     = (const float*)d_in[3];
    const float* convW    = (const float*)d_in[4];
    const float* bnG      = (const float*)d_in[6];
    const float* bnB      = (const float*)d_in[7];
    const float* lnG      = (const float*)d_in[8];
    const float* lnB      = (const float*)d_in[9];
    const float* fc1W     = (const float*)d_in[10];
    const float* fc1B     = (const float*)d_in[11];
    const float* fcsW     = (const float*)d_in[12];
    const float* fcsB     = (const float*)d_in[13];
    const float* foW      = (const float*)d_in[14];
    const float* foB      = (const float*)d_in[15];
    const int*   eidx     = (const int*)d_in[16];
    const int*   batch    = (const int*)d_in[17];
    float* out = (float*)d_out;

    k_zero0<<<(NN * NDIM + 255) / 256, 256>>>();
    k_embed<<<(NN + 7) / 8, 64>>>(x, embW, embB);
    k_prepw<<<(NCONV * 128 * KPAD + 255) / 256, 256>>>(convW);
    k_prepea<<<(int)(((size_t)NE * KPAD + 255) / 256), 256>>>(edge_attr);
    // counting sort of edges by dst
    k_hist<<<(NE + 255) / 256, 256>>>(eidx);
    k_scan<<<1, 1024>>>();
    k_scatter<<<(NE + 255) / 256, 256>>>(eidx);

    for (int l = 0; l < NCONV; l++) {
        k_pgemm16<<<dim3((NN + 63) / 64, 2), 256>>>(convW, l);
        k_ewfused16<<<NE / 64, 256>>>(eidx, l);
        k_stats<<<1, 128>>>(bnG, bnB, l);
        k_applyS<<<(NE + 8 * SLEN - 1) / (8 * SLEN), 256>>>();
        k_node<<<(NN + 3) / 4, 128>>>(lnG, lnB, l);
    }

    k_pool<<<(NN * 64 + 255) / 256, 256>>>(batch);
    k_mlp<<<NG, 128>>>(fc1W, fc1B, fcsW, fcsB, foW, foB, out);
}

// round 17
// speedup vs baseline: 1.1286x; 1.1286x over previous
#include <cuda_runtime.h>
#include <cuda_fp16.h>
#include <stdint.h>
#include <math.h>

#define NN 30000
#define NE 480000
#define NG 300
#define NDIM 64
#define EDIM 41
#define NCONV 6
#define EPSV 1e-5f
#define KPAD 48
#define KP2 72

// ---- scratch (static device globals; no runtime allocation) ----
__device__ float g_nf[NN * NDIM];
__device__ __half g_P[NN * 256];             // fp16 (15.4 MB, L2-resident)
__device__ __half g_z[(size_t)NE * 128];     // per-layer pre-BN z (123 MB)
__device__ __half g_w3[NCONV * 128 * KPAD];
__device__ __half g_ea16[(size_t)NE * KPAD];
__device__ float g_agg[NN * NDIM];
__device__ float g_stats[256];
__device__ float g_sb[256];
__device__ float g_gsum[NG * NDIM];
__device__ float g_gcnt[NG];

__device__ __forceinline__ float sp_f(float x) {
    // softplus: fast log/exp; for x>15, log1p(e^-x) < 3e-7 -> x
    return x > 15.f ? x : __logf(1.f + __expf(x));
}
__device__ __forceinline__ float sig_f(float x) {
    return __fdividef(1.f, 1.f + __expf(-x));
}

#define MMA_F16(c0,c1,c2,c3,a0,a1,a2,a3,b0,b1) \
  asm volatile("mma.sync.aligned.m16n8k16.row.col.f32.f16.f16.f32 " \
      "{%0,%1,%2,%3}, {%4,%5,%6,%7}, {%8,%9}, {%0,%1,%2,%3};" \
      : "+f"(c0),"+f"(c1),"+f"(c2),"+f"(c3) \
      : "r"(a0),"r"(a1),"r"(a2),"r"(a3),"r"(b0),"r"(b1))

// ---------------- embed ----------------
__global__ void k_embed(const float* __restrict__ x,
                        const float* __restrict__ embW,
                        const float* __restrict__ embB) {
    int c = threadIdx.x;
    float w[92];
#pragma unroll
    for (int k = 0; k < 92; k++) w[k] = embW[k * 64 + c];
    float b = embB[c];
    __shared__ float xs[8][92];
    int v0 = blockIdx.x * 8;
    for (int i = threadIdx.x; i < 8 * 92; i += 64) {
        int n = i / 92, k = i % 92;
        int v = v0 + n;
        xs[n][k] = (v < NN) ? x[v * 92 + k] : 0.f;
    }
    __syncthreads();
#pragma unroll 2
    for (int n = 0; n < 8; n++) {
        int v = v0 + n;
        if (v >= NN) break;
        float acc = b;
#pragma unroll
        for (int k = 0; k < 92; k++) acc += xs[n][k] * w[k];
        g_nf[v * 64 + c] = acc;
    }
}

// ---------------- prep: weights + edge_attr to fp16 ----------------
__global__ void k_prepw(const float* __restrict__ convW) {
    int i = blockIdx.x * 256 + threadIdx.x;
    if (i >= NCONV * 128 * KPAD) return;
    int n = i / KPAD, k = i - n * KPAD;
    int l = n >> 7, c = n & 127;
    float v = (k < EDIM) ? convW[(l * 169 + 128 + k) * 128 + c] : 0.f;
    g_w3[i] = __float2half(v);
}

__global__ void k_prepea(const float* __restrict__ ea) {
    size_t i = (size_t)blockIdx.x * 256 + threadIdx.x;
    if (i >= (size_t)NE * KPAD) return;
    size_t e = i / KPAD;
    int k = (int)(i - e * KPAD);
    g_ea16[i] = __float2half((k < EDIM) ? ea[e * EDIM + k] : 0.f);
}

// ---------------- launch-level zero ----------------
__global__ void k_zero0() {
    int i = blockIdx.x * blockDim.x + threadIdx.x;
    if (i < NN * NDIM) g_agg[i] = 0.f;
    if (i < 256) g_stats[i] = 0.f;
    if (i < NG * NDIM) g_gsum[i] = 0.f;
    if (i < NG) g_gcnt[i] = 0.f;
}

// ---------------- P = nf @ [W_dst | W_src] via fp16 mma ----------------
__global__ void k_pgemm16(const float* __restrict__ convW, int l) {
    __shared__ __half Ah[64 * KP2];
    __shared__ __half Bh[128 * KP2];
    int tid = threadIdx.x;
    int m0 = blockIdx.x * 64;
    int half_id = blockIdx.y;

    for (int idx = tid; idx < 64 * 64; idx += 256) {
        int r = idx >> 6, k = idx & 63;
        int v = m0 + r;
        Ah[r * KP2 + k] = __float2half((v < NN) ? g_nf[v * 64 + k] : 0.f);
    }
    const float* W = convW + (l * 169 + half_id * 64) * 128;
    for (int idx = tid; idx < 128 * 64; idx += 256) {
        int k = idx >> 7, n = idx & 127;
        Bh[n * KP2 + k] = __float2half(W[k * 128 + n]);
    }
    __syncthreads();

    int w = tid >> 5, lane = tid & 31;
    int wm = w & 3, wn = w >> 2;
    int g = lane >> 2, tq = lane & 3;
    float acc[32];
#pragma unroll
    for (int i = 0; i < 32; i++) acc[i] = 0.f;
    int ar0 = wm * 16 + g;

#pragma unroll
    for (int ks = 0; ks < 4; ks++) {
        int kb = ks * 16 + tq * 2;
        uint32_t a0 = *(const uint32_t*)&Ah[ar0 * KP2 + kb];
        uint32_t a1 = *(const uint32_t*)&Ah[(ar0 + 8) * KP2 + kb];
        uint32_t a2 = *(const uint32_t*)&Ah[ar0 * KP2 + kb + 8];
        uint32_t a3 = *(const uint32_t*)&Ah[(ar0 + 8) * KP2 + kb + 8];
#pragma unroll
        for (int ns = 0; ns < 8; ns++) {
            int bn = wn * 64 + ns * 8 + g;
            uint32_t b0 = *(const uint32_t*)&Bh[bn * KP2 + kb];
            uint32_t b1 = *(const uint32_t*)&Bh[bn * KP2 + kb + 8];
            float* c = acc + ns * 4;
            MMA_F16(c[0], c[1], c[2], c[3], a0, a1, a2, a3, b0, b1);
        }
    }

    int row0 = m0 + wm * 16 + g;
#pragma unroll
    for (int ns = 0; ns < 8; ns++) {
        int col = half_id * 128 + wn * 64 + ns * 8 + tq * 2;
        if (row0 < NN)
            ((__half2*)g_P)[((size_t)row0 * 256 + col) >> 1] =
                __floats2half2_rn(acc[ns * 4 + 0], acc[ns * 4 + 1]);
        if (row0 + 8 < NN)
            ((__half2*)g_P)[((size_t)(row0 + 8) * 256 + col) >> 1] =
                __floats2half2_rn(acc[ns * 4 + 2], acc[ns * 4 + 3]);
    }
}

// ---------------- fused: z = ea@W3 + P1[dst] + P2[src]; z store (coalesced); BN stats ----------------
__global__ void k_ewfused16(const int* __restrict__ eidx, int l) {
    __shared__ __half Ah[64 * KPAD];
    __shared__ __half Bh[128 * KPAD];
    __shared__ float sred[256];
    int tid = threadIdx.x;
    int m0 = blockIdx.x * 64;

    int w = tid >> 5, lane = tid & 31;
    int wm = w & 3, wn = w >> 2;
    int g = lane >> 2, tq = lane & 3;

    // ---- prefetch indices + P gathers (independent of MMA) ----
    int r0 = wm * 16 + g, r1 = r0 + 8;
    int d0 = eidx[NE + m0 + r0], s0 = eidx[m0 + r0];
    int d1 = eidx[NE + m0 + r1], s1 = eidx[m0 + r1];
    __half2 pd0[8], ps0[8], pd1[8], ps1[8];
#pragma unroll
    for (int ns = 0; ns < 8; ns++) {
        int col = wn * 64 + ns * 8 + tq * 2;
        pd0[ns] = *(const __half2*)&g_P[(size_t)d0 * 256 + col];
        ps0[ns] = *(const __half2*)&g_P[(size_t)s0 * 256 + 128 + col];
        pd1[ns] = *(const __half2*)&g_P[(size_t)d1 * 256 + col];
        ps1[ns] = *(const __half2*)&g_P[(size_t)s1 * 256 + 128 + col];
    }

    sred[tid] = 0.f;
    const uint32_t* easrc = (const uint32_t*)(g_ea16 + (size_t)m0 * KPAD);
    for (int idx = tid; idx < 64 * KPAD / 2; idx += 256)
        ((uint32_t*)Ah)[idx] = easrc[idx];
    const uint32_t* w3 = (const uint32_t*)(g_w3 + l * 128 * KPAD);
    for (int idx = tid; idx < 128 * KPAD / 2; idx += 256)
        ((uint32_t*)Bh)[idx] = w3[idx];
    __syncthreads();

    float acc[32];
#pragma unroll
    for (int i = 0; i < 32; i++) acc[i] = 0.f;
    int ar0 = wm * 16 + g;

#pragma unroll
    for (int ks = 0; ks < 3; ks++) {
        int kb = ks * 16 + tq * 2;
        uint32_t a0 = *(const uint32_t*)&Ah[ar0 * KPAD + kb];
        uint32_t a1 = *(const uint32_t*)&Ah[(ar0 + 8) * KPAD + kb];
        uint32_t a2 = *(const uint32_t*)&Ah[ar0 * KPAD + kb + 8];
        uint32_t a3 = *(const uint32_t*)&Ah[(ar0 + 8) * KPAD + kb + 8];
#pragma unroll
        for (int ns = 0; ns < 8; ns++) {
            int bn = wn * 64 + ns * 8 + g;
            uint32_t b0 = *(const uint32_t*)&Bh[bn * KPAD + kb];
            uint32_t b1 = *(const uint32_t*)&Bh[bn * KPAD + kb + 8];
            float* c = acc + ns * 4;
            MMA_F16(c[0], c[1], c[2], c[3], a0, a1, a2, a3, b0, b1);
        }
    }

#pragma unroll
    for (int ns = 0; ns < 8; ns++) {
        int col = wn * 64 + ns * 8 + tq * 2;
        float2 fd0 = __half22float2(pd0[ns]);
        float2 fs0 = __half22float2(ps0[ns]);
        float2 fd1 = __half22float2(pd1[ns]);
        float2 fs1 = __half22float2(ps1[ns]);
        float z00 = acc[ns * 4 + 0] + fd0.x + fs0.x;
        float z01 = acc[ns * 4 + 1] + fd0.y + fs0.y;
        float z10 = acc[ns * 4 + 2] + fd1.x + fs1.x;
        float z11 = acc[ns * 4 + 3] + fd1.y + fs1.y;
        ((__half2*)g_z)[((size_t)(m0 + r0) * 128 + col) >> 1] = __floats2half2_rn(z00, z01);
        ((__half2*)g_z)[((size_t)(m0 + r1) * 128 + col) >> 1] = __floats2half2_rn(z10, z11);
        acc[ns * 4 + 0] = z00 + z10;
        acc[ns * 4 + 1] = z01 + z11;
        acc[ns * 4 + 2] = z00 * z00 + z10 * z10;
        acc[ns * 4 + 3] = z01 * z01 + z11 * z11;
    }
#pragma unroll
    for (int off = 4; off <= 16; off <<= 1) {
#pragma unroll
        for (int i = 0; i < 32; i++)
            acc[i] += __shfl_xor_sync(0xffffffff, acc[i], off);
    }
    if (g == 0) {
#pragma unroll
        for (int ns = 0; ns < 8; ns++) {
            int col = wn * 64 + ns * 8 + tq * 2;
            atomicAdd(&sred[col],       acc[ns * 4 + 0]);
            atomicAdd(&sred[col + 1],   acc[ns * 4 + 1]);
            atomicAdd(&sred[128 + col], acc[ns * 4 + 2]);
            atomicAdd(&sred[129 + col], acc[ns * 4 + 3]);
        }
    }
    __syncthreads();
    atomicAdd(&g_stats[tid], sred[tid]);
}

// ---------------- finalize BN stats -> scale/bias (self-zero stats) ----------------
__global__ void k_stats(const float* __restrict__ bnG,
                        const float* __restrict__ bnB, int l) {
    int c = threadIdx.x;
    float inv = 1.f / (float)NE;
    float mu = g_stats[c] * inv;
    float var = g_stats[128 + c] * inv - mu * mu;
    float sc = rsqrtf(var + EPSV) * bnG[l * 128 + c];
    g_sb[c] = sc;
    g_sb[128 + c] = bnB[l * 128 + c] - mu * sc;
    g_stats[c] = 0.f;
    g_stats[128 + c] = 0.f;
}

// ---------------- apply: wide z loads (uint2/lane, shfl pair), BN + gate + scatter-add ----------------
// Warp handles one edge per iter: lanes 0..15 load z1 cols 4q..4q+3, lanes 16..31 load
// z2 cols 4q..4q+3; shfl_xor(16) exchanges so every lane computes 2 gate columns.
__global__ void k_apply(const int* __restrict__ eidx) {
    __shared__ float sb[256];
    __shared__ int sdst[256];
    int tid = threadIdx.x;
    sb[tid] = g_sb[tid];
    int e0 = blockIdx.x * 256;
    sdst[tid] = eidx[NE + e0 + tid];
    __syncthreads();
    int wid = tid >> 5, lane = tid & 31;
    int hi = lane >> 4;           // 0: z1 loader, 1: z2 loader
    int q = lane & 15;
    int cg = q * 4;               // 4-column group
    int myc = cg + hi * 2;        // my 2 output columns
    float s1a = sb[myc],       s1b = sb[myc + 1];
    float b1a = sb[128 + myc], b1b = sb[129 + myc];
    float s2a = sb[64 + myc],  s2b = sb[65 + myc];
    float b2a = sb[192 + myc], b2b = sb[193 + myc];
    int off = hi * 64 + cg;       // load offset within the 128-half row
#pragma unroll 2
    for (int i = 0; i < 32; i++) {
        int er = 8 * i + wid;
        size_t e = (size_t)(e0 + er);
        uint2 v = *(const uint2*)&g_z[e * 128 + off];
        uint32_t ox = __shfl_xor_sync(0xffffffffu, v.x, 16);
        uint32_t oy = __shfl_xor_sync(0xffffffffu, v.y, 16);
        uint32_t z1w = hi ? oy : v.x;   // z1 cols myc, myc+1
        uint32_t z2w = hi ? v.y : ox;   // z2 cols myc, myc+1
        float2 f1 = __half22float2(*(__half2*)&z1w);
        float2 f2 = __half22float2(*(__half2*)&z2w);
        float z1a = f1.x * s1a + b1a;
        float z1b = f1.y * s1b + b1b;
        float z2a = f2.x * s2a + b2a;
        float z2b = f2.y * s2b + b2b;
        int d = sdst[er];
        atomicAdd(&g_agg[(size_t)d * 64 + myc],     sig_f(z1a) * sp_f(z2a));
        atomicAdd(&g_agg[(size_t)d * 64 + myc + 1], sig_f(z1b) * sp_f(z2b));
    }
}

// ---------------- node update (self-zero agg) ----------------
__global__ void k_node(const float* __restrict__ lnG,
                       const float* __restrict__ lnB, int l) {
    int v = blockIdx.x * 4 + (threadIdx.x >> 5);
    int lane = threadIdx.x & 31;
    if (v >= NN) return;
    float a0 = g_agg[v * 64 + lane];
    float a1 = g_agg[v * 64 + 32 + lane];
    g_agg[v * 64 + lane] = 0.f;
    g_agg[v * 64 + 32 + lane] = 0.f;
    float s = a0 + a1;
    float sq = a0 * a0 + a1 * a1;
#pragma unroll
    for (int o = 16; o > 0; o >>= 1) {
        s  += __shfl_xor_sync(0xffffffff, s, o);
        sq += __shfl_xor_sync(0xffffffff, sq, o);
    }
    float mu = s * (1.f / 64.f);
    float var = sq * (1.f / 64.f) - mu * mu;
    float rs = rsqrtf(var + EPSV);
    float l0 = (a0 - mu) * rs * lnG[l * 64 + lane] + lnB[l * 64 + lane];
    float l1 = (a1 - mu) * rs * lnG[l * 64 + 32 + lane] + lnB[l * 64 + 32 + lane];
    g_nf[v * 64 + lane]      = sp_f(l0 + g_nf[v * 64 + lane]);
    g_nf[v * 64 + 32 + lane] = sp_f(l1 + g_nf[v * 64 + 32 + lane]);
}

// ---------------- pooling ----------------
__global__ void k_pool(const int* __restrict__ batch) {
    int tid = blockIdx.x * blockDim.x + threadIdx.x;
    int v = tid >> 6;
    int c = tid & 63;
    if (v >= NN) return;
    int g = batch[v];
    atomicAdd(&g_gsum[g * 64 + c], g_nf[v * 64 + c]);
    if (c == 0) atomicAdd(&g_gcnt[g], 1.f);
}

// ---------------- final MLP head ----------------
__global__ void k_mlp(const float* __restrict__ fc1W, const float* __restrict__ fc1B,
                      const float* __restrict__ fcsW, const float* __restrict__ fcsB,
                      const float* __restrict__ foW, const float* __restrict__ foB,
                      float* __restrict__ out) {
    int g = blockIdx.x;
    int c = threadIdx.x;
    __shared__ float s[64];
    __shared__ float h[128];
    __shared__ float red[128];

    if (c < 64) {
        float cnt = g_gcnt[g];
        s[c] = g_gsum[g * 64 + c] / fmaxf(cnt, 1.f);
    }
    __syncthreads();
    float acc = fc1B[c];
#pragma unroll 4
    for (int k = 0; k < 64; k++) acc += s[k] * fc1W[k * 128 + c];
    h[c] = sp_f(acc);
    __syncthreads();
    for (int lh = 0; lh < 3; lh++) {
        float a = fcsB[lh * 128 + c];
#pragma unroll 4
        for (int k = 0; k < 128; k++) a += h[k] * fcsW[(lh * 128 + k) * 128 + c];
        __syncthreads();
        h[c] = sp_f(a);
        __syncthreads();
    }
    red[c] = h[c] * foW[c];
    __syncthreads();
#pragma unroll
    for (int o = 64; o > 0; o >>= 1) {
        if (c < o) red[c] += red[c + o];
        __syncthreads();
    }
    if (c == 0) out[g] = red[0] + foB[0];
}

// ---------------- launch ----------------
extern "C" void kernel_launch(void* const* d_in, const int* in_sizes, int n_in,
                              void* d_out, int out_size) {
    const float* x        = (const float*)d_in[0];
    const float* edge_attr= (const float*)d_in[1];
    const float* embW     = (const float*)d_in[2];
    const float* embB     = (const float*)d_in[3];
    const float* convW    = (const float*)d_in[4];
    const float* bnG      = (const float*)d_in[6];
    const float* bnB      = (const float*)d_in[7];
    const float* lnG      = (const float*)d_in[8];
    const float* lnB      = (const float*)d_in[9];
    const float* fc1W     = (const float*)d_in[10];
    const float* fc1B     = (const float*)d_in[11];
    const float* fcsW     = (const float*)d_in[12];
    const float* fcsB     = (const float*)d_in[13];
    const float* foW      = (const float*)d_in[14];
    const float* foB      = (const float*)d_in[15];
    const int*   eidx     = (const int*)d_in[16];
    const int*   batch    = (const int*)d_in[17];
    float* out = (float*)d_out;

    k_zero0<<<(NN * NDIM + 255) / 256, 256>>>();
    k_embed<<<(NN + 7) / 8, 64>>>(x, embW, embB);
    k_prepw<<<(NCONV * 128 * KPAD + 255) / 256, 256>>>(convW);
    k_prepea<<<(int)(((size_t)NE * KPAD + 255) / 256), 256>>>(edge_attr);

    for (int l = 0; l < NCONV; l++) {
        k_pgemm16<<<dim3((NN + 63) / 64, 2), 256>>>(convW, l);
        k_ewfused16<<<NE / 64, 256>>>(eidx, l);
        k_stats<<<1, 128>>>(bnG, bnB, l);
        k_apply<<<NE / 256, 256>>>(eidx);
        k_node<<<(NN + 3) / 4, 128>>>(lnG, lnB, l);
    }

    k_pool<<<(NN * 64 + 255) / 256, 256>>>(batch);
    k_mlp<<<NG, 128>>>(fc1W, fc1B, fcsW, fcsB, foW, foB, out);
}